// round 2
// baseline (speedup 1.0000x reference)
#include <cuda_runtime.h>
#include <cstdint>
#include <math.h>

#define BB 64
#define SS 512
#define EE 256
#define HH 512
#define HD 1024
#define G4 2048              // 4*H
#define NG 4096              // 2 dirs * 4H
#define TT 9

// ---------------- static device buffers (no allocation allowed) ----------------
__device__ float d_x0[(size_t)BB * SS * EE];                 // embedded input
__device__ float d_xg0[(size_t)2 * SS * BB * G4];            // layer0 input proj, [d][t][b][gate]
__device__ float d_x1[(size_t)BB * SS * HD];                 // layer0 output / layer1 input
__device__ float d_xg1[(size_t)2 * SS * BB * G4];            // layer1 input proj
__device__ float d_x2[(size_t)BB * SS * HD];                 // layer1 output
__device__ float d_logits[(size_t)BB * SS * TT];
__device__ float d_hbuf[2 * 2 * HH * BB];                    // [dir][pingpong][k][m]
__device__ float d_llh[BB];
__device__ unsigned g_bar_cnt;                               // zero-init
__device__ unsigned g_bar_gen;                               // zero-init

// ---------------- grid barrier (all blocks co-resident) ----------------
__device__ __forceinline__ void grid_barrier(int nb) {
    __syncthreads();
    if (threadIdx.x == 0) {
        __threadfence();
        unsigned g = atomicAdd(&g_bar_gen, 0u);
        unsigned r = atomicAdd(&g_bar_cnt, 1u);
        if (r == (unsigned)nb - 1u) {
            atomicExch(&g_bar_cnt, 0u);
            __threadfence();
            atomicAdd(&g_bar_gen, 1u);
        } else {
            while (atomicAdd(&g_bar_gen, 0u) == g) { __nanosleep(128); }
        }
        __threadfence();
    }
    __syncthreads();
}

// ---------------- embedding gather ----------------
__global__ void k_embed(const int* __restrict__ ids, const float* __restrict__ emb) {
    int row = blockIdx.x;                                    // 0..B*S-1
    const float4* src = (const float4*)(emb + (size_t)ids[row] * EE);
    float4* dst = (float4*)(d_x0 + (size_t)row * EE);
    dst[threadIdx.x] = src[threadIdx.x];                     // 64 threads * float4 = 256
}

// ---------------- tf32 split helper ----------------
__device__ __forceinline__ void split_tf32(float x, unsigned &hi, unsigned &lo) {
    unsigned h;
    asm("cvt.rna.tf32.f32 %0, %1;" : "=r"(h) : "f"(x));
    float hf = __uint_as_float(h);
    unsigned l;
    asm("cvt.rna.tf32.f32 %0, %1;" : "=r"(l) : "f"(x - hf));
    hi = h; lo = l;
}

__device__ __forceinline__ void mma_tf32(float c[4], unsigned a0, unsigned a1,
                                         unsigned a2, unsigned a3,
                                         unsigned b0, unsigned b1) {
    asm volatile(
        "mma.sync.aligned.m16n8k8.row.col.f32.tf32.tf32.f32 "
        "{%0,%1,%2,%3}, {%4,%5,%6,%7}, {%8,%9}, {%0,%1,%2,%3};"
        : "+f"(c[0]), "+f"(c[1]), "+f"(c[2]), "+f"(c[3])
        : "r"(a0), "r"(a1), "r"(a2), "r"(a3), "r"(b0), "r"(b1));
}

// ---------------- input-projection GEMM (3xTF32 tensor cores) ----------------
// xg[d][s][b][g] = A @ W^T + bias.  A: [32768][K] (row m = b*512+s), W: [4096][K].
// Block tile 128x128, BLK_K=16, 8 warps (2x4), warp tile 64x32.
#define SMS 136   // smem row stride (floats) -> conflict-free fragment loads
template <int PH>
__global__ void __launch_bounds__(256) k_gemm_mma(const float* __restrict__ W,
                                                  const float* __restrict__ bih,
                                                  const float* __restrict__ bhh) {
    constexpr int K = (PH == 0) ? EE : HD;
    const float* A = (PH == 0) ? (const float*)d_x0 : (const float*)d_x1;
    float* xg      = (PH == 0) ? d_xg0 : d_xg1;

    __shared__ unsigned As_hi[16 * SMS];
    __shared__ unsigned As_lo[16 * SMS];
    __shared__ unsigned Ws_hi[16 * SMS];
    __shared__ unsigned Ws_lo[16 * SMS];

    const int m0 = blockIdx.y * 128;
    const int n0 = blockIdx.x * 128;
    const int tid = threadIdx.x;
    const int wid = tid >> 5;
    const int lane = tid & 31;
    const int wm = (wid >> 2) * 64;     // warp m offset (0/64)
    const int wn = (wid & 3) * 32;      // warp n offset
    const int fr = lane >> 2;           // 0..7
    const int fc = lane & 3;            // 0..3

    float acc[4][4][4];
#pragma unroll
    for (int i = 0; i < 4; i++)
#pragma unroll
        for (int j = 0; j < 4; j++)
#pragma unroll
            for (int q = 0; q < 4; q++) acc[i][j][q] = 0.f;

    const int r = tid >> 1;             // 0..127
    const int cb = (tid & 1) * 8;       // 0 or 8

    for (int k0 = 0; k0 < K; k0 += 16) {
        // ---- load + split 128x16 tiles of A and W into smem (k-major) ----
        {
            const float* ap = A + (size_t)(m0 + r) * K + k0 + cb;
            float4 v0 = *(const float4*)ap;
            float4 v1 = *(const float4*)(ap + 4);
            float av[8] = {v0.x, v0.y, v0.z, v0.w, v1.x, v1.y, v1.z, v1.w};
#pragma unroll
            for (int j = 0; j < 8; j++) {
                unsigned h, l; split_tf32(av[j], h, l);
                As_hi[(cb + j) * SMS + r] = h;
                As_lo[(cb + j) * SMS + r] = l;
            }
            const float* bp = W + (size_t)(n0 + r) * K + k0 + cb;
            float4 w0 = *(const float4*)bp;
            float4 w1 = *(const float4*)(bp + 4);
            float wv[8] = {w0.x, w0.y, w0.z, w0.w, w1.x, w1.y, w1.z, w1.w};
#pragma unroll
            for (int j = 0; j < 8; j++) {
                unsigned h, l; split_tf32(wv[j], h, l);
                Ws_hi[(cb + j) * SMS + r] = h;
                Ws_lo[(cb + j) * SMS + r] = l;
            }
        }
        __syncthreads();

#pragma unroll
        for (int kk = 0; kk < 16; kk += 8) {
            unsigned ah[4][4], al[4][4], bh[4][2], bl[4][2];
#pragma unroll
            for (int mi = 0; mi < 4; mi++) {
                int mb = wm + mi * 16;
                ah[mi][0] = As_hi[(kk + fc) * SMS + mb + fr];
                ah[mi][1] = As_hi[(kk + fc) * SMS + mb + fr + 8];
                ah[mi][2] = As_hi[(kk + fc + 4) * SMS + mb + fr];
                ah[mi][3] = As_hi[(kk + fc + 4) * SMS + mb + fr + 8];
                al[mi][0] = As_lo[(kk + fc) * SMS + mb + fr];
                al[mi][1] = As_lo[(kk + fc) * SMS + mb + fr + 8];
                al[mi][2] = As_lo[(kk + fc + 4) * SMS + mb + fr];
                al[mi][3] = As_lo[(kk + fc + 4) * SMS + mb + fr + 8];
            }
#pragma unroll
            for (int ni = 0; ni < 4; ni++) {
                int nb = wn + ni * 8;
                bh[ni][0] = Ws_hi[(kk + fc) * SMS + nb + fr];
                bh[ni][1] = Ws_hi[(kk + fc + 4) * SMS + nb + fr];
                bl[ni][0] = Ws_lo[(kk + fc) * SMS + nb + fr];
                bl[ni][1] = Ws_lo[(kk + fc + 4) * SMS + nb + fr];
            }
#pragma unroll
            for (int mi = 0; mi < 4; mi++)
#pragma unroll
                for (int ni = 0; ni < 4; ni++) {
                    mma_tf32(acc[mi][ni], ah[mi][0], ah[mi][1], ah[mi][2], ah[mi][3],
                             bh[ni][0], bh[ni][1]);
                    mma_tf32(acc[mi][ni], ah[mi][0], ah[mi][1], ah[mi][2], ah[mi][3],
                             bl[ni][0], bl[ni][1]);
                    mma_tf32(acc[mi][ni], al[mi][0], al[mi][1], al[mi][2], al[mi][3],
                             bh[ni][0], bh[ni][1]);
                }
        }
        __syncthreads();
    }

    // ---- epilogue: bias + scatter to xg[d][s][b][gate] ----
#pragma unroll
    for (int ni = 0; ni < 4; ni++) {
        int ncol = n0 + wn + ni * 8 + 2 * fc;          // even col of the pair
        float bias0 = bih[ncol] + bhh[ncol];
        float bias1 = bih[ncol + 1] + bhh[ncol + 1];
        int d = ncol >> 11;
        int gate = ncol & 2047;
#pragma unroll
        for (int mi = 0; mi < 4; mi++) {
#pragma unroll
            for (int half = 0; half < 2; half++) {
                int m = m0 + wm + mi * 16 + fr + half * 8;
                int b = m >> 9;
                int s = m & 511;
                float* dst = xg + ((size_t)(d * SS + s) * BB + b) * G4 + gate;
                float2 v;
                v.x = acc[mi][ni][half * 2 + 0] + bias0;
                v.y = acc[mi][ni][half * 2 + 1] + bias1;
                *(float2*)dst = v;
            }
        }
    }
}

// ---------------- persistent bidirectional LSTM scan (fp32) ----------------
template <int PH>
__global__ void __launch_bounds__(128, 1) k_scan(const float* __restrict__ whh, int nb) {
    extern __shared__ float sm[];
    float* ws = sm;                       // [32][513]  weights, resident across all steps
    float* hs = sm + 32 * 513;            // [32][64]   h staging (k-major)
    float* Gs = hs + 32 * 64;             // [64][32]   gate pre-activations

    const float* xg = (PH == 0) ? d_xg0 : d_xg1;
    float* xout     = (PH == 0) ? d_x1  : d_x2;

    const int tid = threadIdx.x;
    const int d = blockIdx.x >> 6;        // direction
    const int jg = blockIdx.x & 63;
    const int j0 = jg * 8;                // hidden-unit base

    for (int idx = tid; idx < 32 * HH; idx += 128) {
        int c = idx >> 9;
        int k = idx & 511;
        int g = c >> 3, jj = c & 7;
        ws[c * 513 + k] = whh[((size_t)d * G4 + (size_t)g * HH + j0 + jj) * HH + k];
    }
    for (int idx = tid; idx < 8 * BB; idx += 128) {
        int jj = idx >> 6, m = idx & 63;
        d_hbuf[((d * 2 + 0) * HH + j0 + jj) * BB + m] = 0.f;
    }
    grid_barrier(nb);

    const int tm = tid >> 4;              // 0..7  (m group)
    const int tc = tid & 15;              // 0..15 (col pair)
    const int s0 = tid * 4;
    const int mm = s0 >> 3;               // batch index owned for gate phase
    const int jb = s0 & 7;                // 0 or 4

    float creg[4] = {0.f, 0.f, 0.f, 0.f};

    for (int t = 0; t < SS; t++) {
        const int tt = d ? (SS - 1 - t) : t;
        const float* hsrc = d_hbuf + ((size_t)(d * 2 + (t & 1)) * HH) * BB;

        float acc[8][2];
#pragma unroll
        for (int i = 0; i < 8; i++) { acc[i][0] = 0.f; acc[i][1] = 0.f; }

        for (int k0 = 0; k0 < HH; k0 += 32) {
            const float4* src4 = (const float4*)(hsrc + k0 * BB);
            float4* dst4 = (float4*)hs;
#pragma unroll
            for (int q = 0; q < 4; q++) dst4[tid + 128 * q] = src4[tid + 128 * q];
            __syncthreads();

            const float* wsb = ws + (2 * tc) * 513 + k0;
#pragma unroll
            for (int kk = 0; kk < 32; kk++) {
                float b0 = wsb[kk];
                float b1 = wsb[513 + kk];
                const float* ha = hs + kk * 64 + tm * 8;
                float4 a0 = *(const float4*)ha;
                float4 a1 = *(const float4*)(ha + 4);
                float a[8];
                a[0]=a0.x;a[1]=a0.y;a[2]=a0.z;a[3]=a0.w;a[4]=a1.x;a[5]=a1.y;a[6]=a1.z;a[7]=a1.w;
#pragma unroll
                for (int i = 0; i < 8; i++) {
                    acc[i][0] += a[i] * b0;
                    acc[i][1] += a[i] * b1;
                }
            }
            __syncthreads();
        }
#pragma unroll
        for (int i = 0; i < 8; i++) {
            Gs[(tm * 8 + i) * 32 + 2 * tc]     = acc[i][0];
            Gs[(tm * 8 + i) * 32 + 2 * tc + 1] = acc[i][1];
        }
        __syncthreads();

        const float* xgb = xg + (((size_t)d * SS + tt) * BB + mm) * G4 + j0 + jb;
        float4 gi = *(const float4*)(xgb + 0 * HH);
        float4 gf = *(const float4*)(xgb + 1 * HH);
        float4 gg = *(const float4*)(xgb + 2 * HH);
        float4 go = *(const float4*)(xgb + 3 * HH);
        float hnew[4];
        const float* gim = (const float*)&gi;
        const float* gfm = (const float*)&gf;
        const float* ggm = (const float*)&gg;
        const float* gom = (const float*)&go;
#pragma unroll
        for (int q = 0; q < 4; q++) {
            float vi = gim[q] + Gs[mm * 32 + 0 * 8 + jb + q];
            float vf = gfm[q] + Gs[mm * 32 + 1 * 8 + jb + q];
            float vg = ggm[q] + Gs[mm * 32 + 2 * 8 + jb + q];
            float vo = gom[q] + Gs[mm * 32 + 3 * 8 + jb + q];
            float si = 1.f / (1.f + expf(-vi));
            float sf = 1.f / (1.f + expf(-vf));
            float so = 1.f / (1.f + expf(-vo));
            float tg = tanhf(vg);
            creg[q] = sf * creg[q] + si * tg;
            hnew[q] = so * tanhf(creg[q]);
        }
        float* hdst = d_hbuf + ((size_t)(d * 2 + ((t + 1) & 1)) * HH) * BB;
#pragma unroll
        for (int q = 0; q < 4; q++) hdst[(j0 + jb + q) * BB + mm] = hnew[q];
        float4 hv;
        hv.x = hnew[0]; hv.y = hnew[1]; hv.z = hnew[2]; hv.w = hnew[3];
        *(float4*)(xout + ((size_t)mm * SS + tt) * HD + d * HH + j0 + jb) = hv;

        grid_barrier(nb);
    }
}

// ---------------- classifier: logits = x2 @ cls_w^T + cls_b ----------------
__global__ void k_logits(const float* __restrict__ clsw, const float* __restrict__ clsb) {
    int gwarp = (blockIdx.x * blockDim.x + threadIdx.x) >> 5;
    int lane = threadIdx.x & 31;
    if (gwarp >= BB * SS) return;
    const float4* xr = (const float4*)(d_x2 + (size_t)gwarp * HD);
    float4 xv[8];
#pragma unroll
    for (int q = 0; q < 8; q++) xv[q] = xr[lane + 32 * q];
#pragma unroll
    for (int t = 0; t < TT; t++) {
        const float4* wr = (const float4*)(clsw + (size_t)t * HD);
        float p = 0.f;
#pragma unroll
        for (int q = 0; q < 8; q++) {
            float4 wv = wr[lane + 32 * q];
            p += xv[q].x * wv.x + xv[q].y * wv.y + xv[q].z * wv.z + xv[q].w * wv.w;
        }
#pragma unroll
        for (int o = 16; o > 0; o >>= 1) p += __shfl_down_sync(0xffffffffu, p, o);
        if (lane == 0) d_logits[(size_t)gwarp * TT + t] = p + clsb[t];
    }
}

// ---------------- CRF: fused Viterbi decode + log-partition + numerator ----------------
__global__ void k_crf(const int* __restrict__ labels, const int* __restrict__ vlens,
                      const float* __restrict__ trans, const float* __restrict__ startt,
                      const float* __restrict__ endt, float* __restrict__ out) {
    __shared__ float tr[TT * TT];
    __shared__ float alpha[TT], score[TT];
    __shared__ unsigned char hist[SS][TT];
    __shared__ float logZ_s;
    __shared__ int blast_s;

    const int b = blockIdx.x;
    const int tid = threadIdx.x;
    const int vl = vlens[b];
    const float* lg = d_logits + (size_t)b * SS * TT;
    const int* lab = labels + (size_t)b * SS;

    for (int i = tid; i < TT * TT; i += 32) tr[i] = trans[i];
    if (tid < TT) {
        float e = lg[tid];
        alpha[tid] = startt[tid] + e;
        score[tid] = startt[tid] + e;
    }
    __syncwarp();

    for (int t = 1; t < SS; t++) {
        float ns = 0.f, na = 0.f;
        int barg = 0;
        if (tid < TT) {
            float em = lg[t * TT + tid];
            float best = -1e30f, mx = -1e30f;
#pragma unroll
            for (int i = 0; i < TT; i++) {
                float v = score[i] + tr[i * TT + tid];
                if (v > best) { best = v; barg = i; }
                float a = alpha[i] + tr[i * TT + tid];
                mx = fmaxf(mx, a);
            }
            float ssum = 0.f;
#pragma unroll
            for (int i = 0; i < TT; i++) ssum += expf(alpha[i] + tr[i * TT + tid] - mx);
            ns = best + em;
            na = mx + logf(ssum) + em;
            hist[t][tid] = (unsigned char)barg;
        }
        __syncwarp();
        if (tid < TT && t < vl) { score[tid] = ns; alpha[tid] = na; }
        __syncwarp();
    }

    if (tid == 0) {
        float best = -1e30f, mx = -1e30f;
        int ba = 0;
        for (int j = 0; j < TT; j++) {
            float v = score[j] + endt[j];
            if (v > best) { best = v; ba = j; }
            mx = fmaxf(mx, alpha[j] + endt[j]);
        }
        float ss = 0.f;
        for (int j = 0; j < TT; j++) ss += expf(alpha[j] + endt[j] - mx);
        logZ_s = mx + logf(ss);
        blast_s = ba;
    }

    float np = 0.f;
    for (int t = 1 + tid; t < SS; t += 32) {
        if (t < vl) np += lg[t * TT + lab[t]] + tr[lab[t - 1] * TT + lab[t]];
    }
#pragma unroll
    for (int o = 16; o > 0; o >>= 1) np += __shfl_down_sync(0xffffffffu, np, o);
    __syncwarp();

    if (tid == 0) {
        float num = startt[lab[0]] + lg[lab[0]] + np + endt[lab[vl - 1]];
        d_llh[b] = num - logZ_s;
        int tag = blast_s;
        out[(size_t)b * SS + SS - 1] = (float)tag;
        for (int t = SS - 1; t >= 1; t--) {
            if (t < vl) tag = hist[t][tag];
            out[(size_t)b * SS + t - 1] = (float)tag;
        }
    }
}

__global__ void k_loss(float* __restrict__ out) {
    __shared__ float s[BB];
    s[threadIdx.x] = d_llh[threadIdx.x];
    __syncthreads();
    if (threadIdx.x == 0) {
        float t = 0.f;
        for (int i = 0; i < BB; i++) t += s[i];
        out[BB * SS] = -t / (float)BB;
    }
}

// ---------------- launch ----------------
extern "C" void kernel_launch(void* const* d_in, const int* in_sizes, int n_in,
                              void* d_out, int out_size) {
    const int*   ids    = (const int*)d_in[0];
    const int*   vlens  = (const int*)d_in[1];
    const int*   labels = (const int*)d_in[2];
    const float* emb    = (const float*)d_in[3];
    const float* w_ih0  = (const float*)d_in[4];
    const float* w_hh0  = (const float*)d_in[5];
    const float* b_ih0  = (const float*)d_in[6];
    const float* b_hh0  = (const float*)d_in[7];
    const float* w_ih1  = (const float*)d_in[8];
    const float* w_hh1  = (const float*)d_in[9];
    const float* b_ih1  = (const float*)d_in[10];
    const float* b_hh1  = (const float*)d_in[11];
    const float* cls_w  = (const float*)d_in[12];
    const float* cls_b  = (const float*)d_in[13];
    const float* trans  = (const float*)d_in[14];
    const float* start_t = (const float*)d_in[15];
    const float* end_t   = (const float*)d_in[16];
    float* out = (float*)d_out;

    const int SCAN_BLOCKS = 128;
    const int SCAN_SMEM = (32 * 513 + 32 * 64 + 64 * 32) * (int)sizeof(float);
    cudaFuncSetAttribute(k_scan<0>, cudaFuncAttributeMaxDynamicSharedMemorySize, SCAN_SMEM);
    cudaFuncSetAttribute(k_scan<1>, cudaFuncAttributeMaxDynamicSharedMemorySize, SCAN_SMEM);

    // 1. embedding
    k_embed<<<BB * SS, 64>>>(ids, emb);
    // 2. layer0 input projection (3xTF32 tensor cores)
    {
        dim3 grid(NG / 128, (BB * SS) / 128);
        k_gemm_mma<0><<<grid, 256>>>(w_ih0, b_ih0, b_hh0);
    }
    // 3. layer0 recurrent scan
    k_scan<0><<<SCAN_BLOCKS, 128, SCAN_SMEM>>>(w_hh0, SCAN_BLOCKS);
    // 4. layer1 input projection
    {
        dim3 grid(NG / 128, (BB * SS) / 128);
        k_gemm_mma<1><<<grid, 256>>>(w_ih1, b_ih1, b_hh1);
    }
    // 5. layer1 recurrent scan
    k_scan<1><<<SCAN_BLOCKS, 128, SCAN_SMEM>>>(w_hh1, SCAN_BLOCKS);
    // 6. classifier
    k_logits<<<(BB * SS) / 8, 256>>>(cls_w, cls_b);
    // 7. CRF decode + loss pieces
    k_crf<<<BB, 32>>>(labels, vlens, trans, start_t, end_t, out);
    // 8. final loss
    k_loss<<<1, BB>>>(out);
}

// round 4
// speedup vs baseline: 2.1029x; 2.1029x over previous
#include <cuda_runtime.h>
#include <cuda_bf16.h>
#include <cstdint>
#include <math.h>

#define BB 64
#define SS 512
#define EE 256
#define HH 512
#define HDI 1024
#define G4 2048              // 4*H
#define NG 4096              // 2 dirs * 4H
#define TT 9
#define MR (BB*SS)           // 32768 rows

typedef __nv_bfloat16 bf16;

// ---------------- static device buffers ----------------
__device__ __align__(256) bf16  d_x0h[(size_t)MR * EE];
__device__ __align__(256) bf16  d_x0l[(size_t)MR * EE];
__device__ __align__(256) bf16  d_w0h[(size_t)NG * EE];
__device__ __align__(256) bf16  d_w0l[(size_t)NG * EE];
__device__ __align__(256) bf16  d_w1h[(size_t)NG * HDI];
__device__ __align__(256) bf16  d_w1l[(size_t)NG * HDI];
__device__ __align__(256) float d_xg0[(size_t)2 * SS * BB * G4];
__device__ __align__(256) float d_xg1[(size_t)2 * SS * BB * G4];
__device__ __align__(256) bf16  d_x1h[(size_t)MR * HDI];
__device__ __align__(256) bf16  d_x1l[(size_t)MR * HDI];
__device__ __align__(256) float d_x2[(size_t)MR * HDI];
__device__ __align__(256) bf16  d_hbh[2 * 2 * BB * HH];    // [dir][pp][m][k]
__device__ __align__(256) bf16  d_hbl[2 * 2 * BB * HH];
__device__ __align__(256) float d_logits[(size_t)MR * TT];
__device__ float d_llh[BB];
__device__ unsigned g_bar_cnt;
__device__ unsigned g_bar_gen;

// ---------------- helpers ----------------
__device__ __forceinline__ void split_bf(float x, bf16 &h, bf16 &l) {
    h = __float2bfloat16(x);
    l = __float2bfloat16(x - __bfloat162float(h));
}
__device__ __forceinline__ unsigned pack2(bf16 a, bf16 b) {
    __nv_bfloat162 v; v.x = a; v.y = b;
    return *(unsigned*)&v;
}
__device__ __forceinline__ void mma_bf16(float* c, unsigned a0, unsigned a1,
                                         unsigned a2, unsigned a3,
                                         unsigned b0, unsigned b1) {
    asm volatile(
        "mma.sync.aligned.m16n8k16.row.col.f32.bf16.bf16.f32 "
        "{%0,%1,%2,%3}, {%4,%5,%6,%7}, {%8,%9}, {%0,%1,%2,%3};"
        : "+f"(c[0]), "+f"(c[1]), "+f"(c[2]), "+f"(c[3])
        : "r"(a0), "r"(a1), "r"(a2), "r"(a3), "r"(b0), "r"(b1));
}
#define CPA16(dst_u32, src) \
    asm volatile("cp.async.cg.shared.global [%0], [%1], 16;" :: "r"(dst_u32), "l"(src))
#define CP_COMMIT() asm volatile("cp.async.commit_group;")
#define CP_WAIT1()  asm volatile("cp.async.wait_group 1;")
#define CP_WAIT0()  asm volatile("cp.async.wait_group 0;")

// ---------------- grid barrier ----------------
__device__ __forceinline__ void grid_barrier(int nb) {
    __syncthreads();
    if (threadIdx.x == 0) {
        __threadfence();
        unsigned g = atomicAdd(&g_bar_gen, 0u);
        unsigned r = atomicAdd(&g_bar_cnt, 1u);
        if (r == (unsigned)nb - 1u) {
            atomicExch(&g_bar_cnt, 0u);
            __threadfence();
            atomicAdd(&g_bar_gen, 1u);
        } else {
            while (atomicAdd(&g_bar_gen, 0u) == g) { __nanosleep(128); }
        }
        __threadfence();
    }
    __syncthreads();
}

// ---------------- embedding gather + bf16 split ----------------
__global__ void k_embed(const int* __restrict__ ids, const float* __restrict__ emb) {
    int row = blockIdx.x;
    int tid = threadIdx.x;                    // 64 threads, 4 cols each
    const float4* src = (const float4*)(emb + (size_t)ids[row] * EE);
    float4 v = src[tid];
    bf16 h0, l0, h1, l1, h2, l2, h3, l3;
    split_bf(v.x, h0, l0); split_bf(v.y, h1, l1);
    split_bf(v.z, h2, l2); split_bf(v.w, h3, l3);
    size_t o = (size_t)row * EE + 4 * tid;
    *(unsigned*)&d_x0h[o]     = pack2(h0, h1);
    *(unsigned*)&d_x0h[o + 2] = pack2(h2, h3);
    *(unsigned*)&d_x0l[o]     = pack2(l0, l1);
    *(unsigned*)&d_x0l[o + 2] = pack2(l2, l3);
}

// ---------------- weight split ----------------
__global__ void k_split(const float* __restrict__ src, bf16* __restrict__ h,
                        bf16* __restrict__ l, int n) {
    int i = blockIdx.x * blockDim.x + threadIdx.x;
    if (i < n) { bf16 a, b; split_bf(src[i], a, b); h[i] = a; l[i] = b; }
}

// ---------------- input-projection GEMM (3xBF16 mma, cp.async pipelined) ----------------
// xg[d][s][b][g] = A @ W^T + bias.  A:[32768][K], W:[4096][K].
// Block 128x128, Kt=32, 8 warps (2x4), warp tile 64x32.
#define GST 40                                   // smem row stride (bf16 elems)
#define GTILE (128 * GST)                        // elems per array per stage
template <int PH>
__global__ void __launch_bounds__(256) k_gemm(const float* __restrict__ bih,
                                              const float* __restrict__ bhh) {
    constexpr int K = (PH == 0) ? EE : HDI;
    const bf16* Ah = (PH == 0) ? d_x0h : d_x1h;
    const bf16* Al = (PH == 0) ? d_x0l : d_x1l;
    const bf16* Wh = (PH == 0) ? d_w0h : d_w1h;
    const bf16* Wl = (PH == 0) ? d_w0l : d_w1l;
    float* xg      = (PH == 0) ? d_xg0 : d_xg1;

    extern __shared__ bf16 sm[];
    const unsigned sm_u32 = (unsigned)__cvta_generic_to_shared(sm);

    const int m0 = blockIdx.y * 128;
    const int n0 = blockIdx.x * 128;
    const int tid = threadIdx.x;
    const int wid = tid >> 5;
    const int lane = tid & 31;
    const int fr = lane >> 2;
    const int fc = lane & 3;
    const int wm = (wid >> 2) * 64;
    const int wn = (wid & 3) * 32;

    float acc[4][4][4];
#pragma unroll
    for (int i = 0; i < 4; i++)
#pragma unroll
        for (int j = 0; j < 4; j++)
#pragma unroll
            for (int q = 0; q < 4; q++) acc[i][j][q] = 0.f;

    const bf16* gsrc[4] = {Ah, Al, Wh, Wl};
    const int rowbase[4] = {m0, m0, n0, n0};

    auto stage = [&](int s, int k0) {
#pragma unroll
        for (int i = 0; i < 8; i++) {
            int slot = tid + 256 * i;
            int arr = slot >> 9;
            int wi = slot & 511;
            int row = wi >> 2;
            int seg = wi & 3;
            const bf16* src = gsrc[arr] + (size_t)(rowbase[arr] + row) * K + k0 + seg * 8;
            unsigned dst = sm_u32 + (unsigned)((s * 4 * GTILE + arr * GTILE + row * GST + seg * 8) * 2);
            CPA16(dst, src);
        }
        CP_COMMIT();
    };

    constexpr int KT = K / 32;
    stage(0, 0);
    for (int it = 0; it < KT; it++) {
        if (it + 1 < KT) { stage((it + 1) & 1, (it + 1) * 32); CP_WAIT1(); }
        else             { CP_WAIT0(); }
        __syncthreads();

        const bf16* Sa  = sm + (it & 1) * 4 * GTILE;
        const bf16* Sal = Sa + GTILE;
        const bf16* Sw  = Sa + 2 * GTILE;
        const bf16* Swl = Sa + 3 * GTILE;
#pragma unroll
        for (int kk = 0; kk < 32; kk += 16) {
            unsigned ah[4][4], al[4][4];
#pragma unroll
            for (int mi = 0; mi < 4; mi++) {
                int r = (wm + mi * 16 + fr) * GST + kk + 2 * fc;
                ah[mi][0] = *(const unsigned*)&Sa[r];
                ah[mi][1] = *(const unsigned*)&Sa[r + 8 * GST];
                ah[mi][2] = *(const unsigned*)&Sa[r + 8];
                ah[mi][3] = *(const unsigned*)&Sa[r + 8 * GST + 8];
                al[mi][0] = *(const unsigned*)&Sal[r];
                al[mi][1] = *(const unsigned*)&Sal[r + 8 * GST];
                al[mi][2] = *(const unsigned*)&Sal[r + 8];
                al[mi][3] = *(const unsigned*)&Sal[r + 8 * GST + 8];
            }
#pragma unroll
            for (int ni = 0; ni < 4; ni++) {
                int r = (wn + ni * 8 + fr) * GST + kk + 2 * fc;
                unsigned bh0 = *(const unsigned*)&Sw[r];
                unsigned bh1 = *(const unsigned*)&Sw[r + 8];
                unsigned bl0 = *(const unsigned*)&Swl[r];
                unsigned bl1 = *(const unsigned*)&Swl[r + 8];
#pragma unroll
                for (int mi = 0; mi < 4; mi++) {
                    mma_bf16(acc[mi][ni], ah[mi][0], ah[mi][1], ah[mi][2], ah[mi][3], bh0, bh1);
                    mma_bf16(acc[mi][ni], ah[mi][0], ah[mi][1], ah[mi][2], ah[mi][3], bl0, bl1);
                    mma_bf16(acc[mi][ni], al[mi][0], al[mi][1], al[mi][2], al[mi][3], bh0, bh1);
                }
            }
        }
        __syncthreads();
    }

    // epilogue: bias + scatter to xg[d][s][b][gate]
#pragma unroll
    for (int ni = 0; ni < 4; ni++) {
        int ncol = n0 + wn + ni * 8 + 2 * fc;
        float bias0 = bih[ncol] + bhh[ncol];
        float bias1 = bih[ncol + 1] + bhh[ncol + 1];
        int d = ncol >> 11;
        int gate = ncol & 2047;
#pragma unroll
        for (int mi = 0; mi < 4; mi++) {
#pragma unroll
            for (int half = 0; half < 2; half++) {
                int m = m0 + wm + mi * 16 + fr + half * 8;
                int b = m >> 9;
                int s = m & 511;
                float2 v;
                v.x = acc[mi][ni][half * 2 + 0] + bias0;
                v.y = acc[mi][ni][half * 2 + 1] + bias1;
                *(float2*)(xg + ((size_t)(d * SS + s) * BB + b) * G4 + gate) = v;
            }
        }
    }
}

// ---------------- persistent bidirectional LSTM scan (3xBF16 mma) ----------------
// 128 blocks: (dir, 8 hidden units). 128 threads (4 warps).
// Per step: G[64b][32c] = h[64][512] @ Wslice^T via m16n8k16, gates in-register.
#define WST 520                                  // ws row stride
#define CST 72                                   // chunk row stride
#define WS_ELEMS (32 * WST)
#define CH_ELEMS (64 * CST)
template <int PH>
__global__ void __launch_bounds__(128, 1) k_scan(const float* __restrict__ whh, int nb) {
    extern __shared__ bf16 sm[];
    bf16* wsh = sm;                              // [32][WST]
    bf16* wsl = sm + WS_ELEMS;
    bf16* chk = sm + 2 * WS_ELEMS;               // [2 stages][2 arrays][64][CST]
    const unsigned chk_u32 = (unsigned)__cvta_generic_to_shared(chk);

    const float* xg = (PH == 0) ? d_xg0 : d_xg1;

    const int tid = threadIdx.x;
    const int d = blockIdx.x >> 6;
    const int j0 = (blockIdx.x & 63) * 8;

    // load + split recurrent weight slice: ws[n][k], n = g*8+jj -> row d*2048+g*512+j0+jj
    for (int idx = tid; idx < 32 * HH; idx += 128) {
        int n = idx >> 9;
        int k = idx & 511;
        int g = n >> 3, jj = n & 7;
        float w = whh[((size_t)d * G4 + (size_t)g * HH + j0 + jj) * HH + k];
        bf16 h, l; split_bf(w, h, l);
        wsh[n * WST + k] = h;
        wsl[n * WST + k] = l;
    }
    // zero ping h (pp=0) for this block's 8 columns
    for (int idx = tid; idx < 64 * 4; idx += 128) {
        int m = idx >> 2, q = idx & 3;
        *(unsigned*)&d_hbh[((size_t)(d * 2 + 0) * BB + m) * HH + j0 + 2 * q] = 0u;
        *(unsigned*)&d_hbl[((size_t)(d * 2 + 0) * BB + m) * HH + j0 + 2 * q] = 0u;
    }
    grid_barrier(nb);

    const int lane = tid & 31;
    const int w = tid >> 5;
    const int fr = lane >> 2;
    const int fc = lane & 3;
    const int m1 = w * 16 + fr;                  // rows m1, m1+8
    const int u0 = 2 * fc;                       // units u0, u0+1

    float creg[4] = {0.f, 0.f, 0.f, 0.f};

    for (int t = 0; t < SS; t++) {
        const int tt = d ? (SS - 1 - t) : t;
        const bf16* hsh = d_hbh + ((size_t)(d * 2 + (t & 1)) * BB) * HH;
        const bf16* hsl = d_hbl + ((size_t)(d * 2 + (t & 1)) * BB) * HH;

        // stage one 64-row x 64-k chunk (hi+lo): 2 arrays * 64 rows * 8 segs = 1024 copies
        auto stg = [&](int c) {
            int k0 = c * 64;
            unsigned sb = chk_u32 + (unsigned)((c & 1) * 2 * CH_ELEMS * 2);
#pragma unroll
            for (int i = 0; i < 8; i++) {
                int slot = tid + 128 * i;        // 0..1023
                int arr = slot >> 9;             // 0: hi, 1: lo
                int wi = slot & 511;
                int row = wi >> 3;               // 0..63
                int seg = wi & 7;                // 0..7 -> k0 + seg*8
                const bf16* src = (arr ? hsl : hsh) + (size_t)row * HH + k0 + seg * 8;
                unsigned dst = sb + (unsigned)((arr * CH_ELEMS + row * CST + seg * 8) * 2);
                CPA16(dst, src);
            }
            CP_COMMIT();
        };
        stg(0);

        // prefetch xg (independent of h)
        const float* xb = xg + ((size_t)(d * SS + tt) * BB + m1) * G4 + j0 + u0;
        float2 xv[8];
#pragma unroll
        for (int g = 0; g < 4; g++) {
            xv[g * 2 + 0] = *(const float2*)(xb + (size_t)g * HH);
            xv[g * 2 + 1] = *(const float2*)(xb + (size_t)g * HH + (size_t)8 * G4);
        }

        float acc[4][4];
#pragma unroll
        for (int g = 0; g < 4; g++)
#pragma unroll
            for (int q = 0; q < 4; q++) acc[g][q] = 0.f;

        for (int c = 0; c < 8; c++) {
            if (c < 7) { stg(c + 1); CP_WAIT1(); }
            else       { CP_WAIT0(); }
            __syncthreads();
            const bf16* Ah = chk + (c & 1) * 2 * CH_ELEMS;
            const bf16* Al = Ah + CH_ELEMS;
#pragma unroll
            for (int kk = 0; kk < 64; kk += 16) {
                int r = (w * 16 + fr) * CST + kk + 2 * fc;
                unsigned a0 = *(const unsigned*)&Ah[r];
                unsigned a1 = *(const unsigned*)&Ah[r + 8 * CST];
                unsigned a2 = *(const unsigned*)&Ah[r + 8];
                unsigned a3 = *(const unsigned*)&Ah[r + 8 * CST + 8];
                unsigned c0 = *(const unsigned*)&Al[r];
                unsigned c1 = *(const unsigned*)&Al[r + 8 * CST];
                unsigned c2 = *(const unsigned*)&Al[r + 8];
                unsigned c3 = *(const unsigned*)&Al[r + 8 * CST + 8];
#pragma unroll
                for (int ni = 0; ni < 4; ni++) {
                    int rb = (ni * 8 + fr) * WST + c * 64 + kk + 2 * fc;
                    unsigned bh0 = *(const unsigned*)&wsh[rb];
                    unsigned bh1 = *(const unsigned*)&wsh[rb + 8];
                    unsigned bl0 = *(const unsigned*)&wsl[rb];
                    unsigned bl1 = *(const unsigned*)&wsl[rb + 8];
                    mma_bf16(acc[ni], a0, a1, a2, a3, bh0, bh1);
                    mma_bf16(acc[ni], a0, a1, a2, a3, bl0, bl1);
                    mma_bf16(acc[ni], c0, c1, c2, c3, bh0, bh1);
                }
            }
            __syncthreads();
        }

        // gates: cell q -> (row m1 + 8*(q>>1), unit u0 + (q&1)), acc[g][q]
        float hn[4];
#pragma unroll
        for (int q = 0; q < 4; q++) {
            int rh = q >> 1;
            float xi = (q & 1) ? xv[0 + rh].y : xv[0 + rh].x;
            float xf = (q & 1) ? xv[2 + rh].y : xv[2 + rh].x;
            float xgv = (q & 1) ? xv[4 + rh].y : xv[4 + rh].x;
            float xo = (q & 1) ? xv[6 + rh].y : xv[6 + rh].x;
            float vi = acc[0][q] + xi;
            float vf = acc[1][q] + xf;
            float vg = acc[2][q] + xgv;
            float vo = acc[3][q] + xo;
            float si = 1.f / (1.f + expf(-vi));
            float sf = 1.f / (1.f + expf(-vf));
            float so = 1.f / (1.f + expf(-vo));
            float tg = tanhf(vg);
            creg[q] = sf * creg[q] + si * tg;
            hn[q] = so * tanhf(creg[q]);
        }

        // write h (hi/lo bf16) to pong buffer + layer output
        bf16 h0h, h0l, h1h, h1l, h2h, h2l, h3h, h3l;
        split_bf(hn[0], h0h, h0l); split_bf(hn[1], h1h, h1l);
        split_bf(hn[2], h2h, h2l); split_bf(hn[3], h3h, h3l);
        unsigned p0h = pack2(h0h, h1h), p0l = pack2(h0l, h1l);
        unsigned p1h = pack2(h2h, h3h), p1l = pack2(h2l, h3l);
        size_t hb = ((size_t)(d * 2 + ((t + 1) & 1)) * BB + m1) * HH + j0 + u0;
        *(unsigned*)&d_hbh[hb] = p0h;
        *(unsigned*)&d_hbl[hb] = p0l;
        *(unsigned*)&d_hbh[hb + (size_t)8 * HH] = p1h;
        *(unsigned*)&d_hbl[hb + (size_t)8 * HH] = p1l;

        if (PH == 0) {
            size_t xo1 = ((size_t)m1 * SS + tt) * HDI + d * HH + j0 + u0;
            *(unsigned*)&d_x1h[xo1] = p0h;
            *(unsigned*)&d_x1l[xo1] = p0l;
            size_t xo2 = ((size_t)(m1 + 8) * SS + tt) * HDI + d * HH + j0 + u0;
            *(unsigned*)&d_x1h[xo2] = p1h;
            *(unsigned*)&d_x1l[xo2] = p1l;
        } else {
            float2 v0; v0.x = hn[0]; v0.y = hn[1];
            float2 v1; v1.x = hn[2]; v1.y = hn[3];
            *(float2*)&d_x2[((size_t)m1 * SS + tt) * HDI + d * HH + j0 + u0] = v0;
            *(float2*)&d_x2[((size_t)(m1 + 8) * SS + tt) * HDI + d * HH + j0 + u0] = v1;
        }

        grid_barrier(nb);
    }
}

// ---------------- classifier ----------------
__global__ void k_logits(const float* __restrict__ clsw, const float* __restrict__ clsb) {
    int gwarp = (blockIdx.x * blockDim.x + threadIdx.x) >> 5;
    int lane = threadIdx.x & 31;
    if (gwarp >= BB * SS) return;
    const float4* xr = (const float4*)(d_x2 + (size_t)gwarp * HDI);
    float4 xv[8];
#pragma unroll
    for (int q = 0; q < 8; q++) xv[q] = xr[lane + 32 * q];
#pragma unroll
    for (int t = 0; t < TT; t++) {
        const float4* wr = (const float4*)(clsw + (size_t)t * HDI);
        float p = 0.f;
#pragma unroll
        for (int q = 0; q < 8; q++) {
            float4 wv = wr[lane + 32 * q];
            p += xv[q].x * wv.x + xv[q].y * wv.y + xv[q].z * wv.z + xv[q].w * wv.w;
        }
#pragma unroll
        for (int o = 16; o > 0; o >>= 1) p += __shfl_down_sync(0xffffffffu, p, o);
        if (lane == 0) d_logits[(size_t)gwarp * TT + t] = p + clsb[t];
    }
}

// ---------------- CRF ----------------
__global__ void k_crf(const int* __restrict__ labels, const int* __restrict__ vlens,
                      const float* __restrict__ trans, const float* __restrict__ startt,
                      const float* __restrict__ endt, float* __restrict__ out) {
    __shared__ float tr[TT * TT];
    __shared__ float alpha[TT], score[TT];
    __shared__ unsigned char hist[SS][TT];
    __shared__ float logZ_s;
    __shared__ int blast_s;

    const int b = blockIdx.x;
    const int tid = threadIdx.x;
    const int vl = vlens[b];
    const float* lg = d_logits + (size_t)b * SS * TT;
    const int* lab = labels + (size_t)b * SS;

    for (int i = tid; i < TT * TT; i += 32) tr[i] = trans[i];
    if (tid < TT) {
        float e = lg[tid];
        alpha[tid] = startt[tid] + e;
        score[tid] = startt[tid] + e;
    }
    __syncwarp();

    for (int t = 1; t < SS; t++) {
        float ns = 0.f, na = 0.f;
        int barg = 0;
        if (tid < TT) {
            float em = lg[t * TT + tid];
            float best = -1e30f, mx = -1e30f;
#pragma unroll
            for (int i = 0; i < TT; i++) {
                float v = score[i] + tr[i * TT + tid];
                if (v > best) { best = v; barg = i; }
                float a = alpha[i] + tr[i * TT + tid];
                mx = fmaxf(mx, a);
            }
            float ssum = 0.f;
#pragma unroll
            for (int i = 0; i < TT; i++) ssum += expf(alpha[i] + tr[i * TT + tid] - mx);
            ns = best + em;
            na = mx + logf(ssum) + em;
            hist[t][tid] = (unsigned char)barg;
        }
        __syncwarp();
        if (tid < TT && t < vl) { score[tid] = ns; alpha[tid] = na; }
        __syncwarp();
    }

    if (tid == 0) {
        float best = -1e30f, mx = -1e30f;
        int ba = 0;
        for (int j = 0; j < TT; j++) {
            float v = score[j] + endt[j];
            if (v > best) { best = v; ba = j; }
            mx = fmaxf(mx, alpha[j] + endt[j]);
        }
        float ss = 0.f;
        for (int j = 0; j < TT; j++) ss += expf(alpha[j] + endt[j] - mx);
        logZ_s = mx + logf(ss);
        blast_s = ba;
    }

    float np = 0.f;
    for (int t = 1 + tid; t < SS; t += 32) {
        if (t < vl) np += lg[t * TT + lab[t]] + tr[lab[t - 1] * TT + lab[t]];
    }
#pragma unroll
    for (int o = 16; o > 0; o >>= 1) np += __shfl_down_sync(0xffffffffu, np, o);
    __syncwarp();

    if (tid == 0) {
        float num = startt[lab[0]] + lg[lab[0]] + np + endt[lab[vl - 1]];
        d_llh[b] = num - logZ_s;
        int tag = blast_s;
        out[(size_t)b * SS + SS - 1] = (float)tag;
        for (int t = SS - 1; t >= 1; t--) {
            if (t < vl) tag = hist[t][tag];
            out[(size_t)b * SS + t - 1] = (float)tag;
        }
    }
}

__global__ void k_loss(float* __restrict__ out) {
    __shared__ float s[BB];
    s[threadIdx.x] = d_llh[threadIdx.x];
    __syncthreads();
    if (threadIdx.x == 0) {
        float t = 0.f;
        for (int i = 0; i < BB; i++) t += s[i];
        out[BB * SS] = -t / (float)BB;
    }
}

// ---------------- launch ----------------
extern "C" void kernel_launch(void* const* d_in, const int* in_sizes, int n_in,
                              void* d_out, int out_size) {
    const int*   ids    = (const int*)d_in[0];
    const int*   vlens  = (const int*)d_in[1];
    const int*   labels = (const int*)d_in[2];
    const float* emb    = (const float*)d_in[3];
    const float* w_ih0  = (const float*)d_in[4];
    const float* w_hh0  = (const float*)d_in[5];
    const float* b_ih0  = (const float*)d_in[6];
    const float* b_hh0  = (const float*)d_in[7];
    const float* w_ih1  = (const float*)d_in[8];
    const float* w_hh1  = (const float*)d_in[9];
    const float* b_ih1  = (const float*)d_in[10];
    const float* b_hh1  = (const float*)d_in[11];
    const float* cls_w  = (const float*)d_in[12];
    const float* cls_b  = (const float*)d_in[13];
    const float* trans  = (const float*)d_in[14];
    const float* start_t = (const float*)d_in[15];
    const float* end_t   = (const float*)d_in[16];
    float* out = (float*)d_out;

    const int GEMM_SMEM = 2 * 4 * GTILE * 2;                       // 81920 B
    const int SCAN_SMEM = (2 * WS_ELEMS + 4 * CH_ELEMS) * 2;       // 103424 B
    cudaFuncSetAttribute(k_gemm<0>, cudaFuncAttributeMaxDynamicSharedMemorySize, GEMM_SMEM);
    cudaFuncSetAttribute(k_gemm<1>, cudaFuncAttributeMaxDynamicSharedMemorySize, GEMM_SMEM);
    cudaFuncSetAttribute(k_scan<0>, cudaFuncAttributeMaxDynamicSharedMemorySize, SCAN_SMEM);
    cudaFuncSetAttribute(k_scan<1>, cudaFuncAttributeMaxDynamicSharedMemorySize, SCAN_SMEM);

    bf16 *w0h, *w0l, *w1h, *w1l;
    cudaGetSymbolAddress((void**)&w0h, d_w0h);
    cudaGetSymbolAddress((void**)&w0l, d_w0l);
    cudaGetSymbolAddress((void**)&w1h, d_w1h);
    cudaGetSymbolAddress((void**)&w1l, d_w1l);

    // prep: embedding + weight splits
    k_embed<<<BB * SS, 64>>>(ids, emb);
    k_split<<<(NG * EE + 255) / 256, 256>>>(w_ih0, w0h, w0l, NG * EE);
    k_split<<<(NG * HDI + 255) / 256, 256>>>(w_ih1, w1h, w1l, NG * HDI);

    dim3 ggrid(NG / 128, MR / 128);
    // layer 0
    k_gemm<0><<<ggrid, 256, GEMM_SMEM>>>(b_ih0, b_hh0);
    k_scan<0><<<128, 128, SCAN_SMEM>>>(w_hh0, 128);
    // layer 1
    k_gemm<1><<<ggrid, 256, GEMM_SMEM>>>(b_ih1, b_hh1);
    k_scan<1><<<128, 128, SCAN_SMEM>>>(w_hh1, 128);
    // classifier + CRF
    k_logits<<<(BB * SS) / 8, 256>>>(cls_w, cls_b);
    k_crf<<<BB, 32>>>(labels, vlens, trans, start_t, end_t, out);
    k_loss<<<1, BB>>>(out);
}